// round 7
// baseline (speedup 1.0000x reference)
#include <cuda_runtime.h>

#define NN     100000
#define EDIM   128
#define QBLKS  512          // qmin partial blocks (one plain-store partial each)

// Persistent device scratch (no allocs in kernel_launch).
__device__ float  g_a[EDIM];
__device__ float  g_b[EDIM];
__device__ float  g_c[EDIM];
__device__ float2 g_T1[NN];                 // (s1, s1 + s3shift)
__device__ float2 g_T2[NN];                 // (s2 + bias, s2 + s3shift + bias)
__device__ int    g_partmin[QBLKS];         // per-block qmin partials

// ───────────── K0: block 0 folds Wo into Wq (coalesced, transposed mapping);
//               blocks 1..QBLKS compute qmin partials (int4 sweep).
__global__ void k0_prep_qmin(const float* __restrict__ Wq, const float* __restrict__ Wo,
                             const int* __restrict__ ei, int E) {
    int bid = blockIdx.x;

    if (bid == 0) {
        // b[j] = Σ_i wo2[i]·Wq[i][j], c[j] = Σ_i wo2[i]·Wq[i][128+j]
        // 256 threads: g = tid>>7 ∈ {0,1} owns i-range [g*64, g*64+64); j = tid&127.
        // Loads are coalesced across j (consecutive floats per row).
        __shared__ float sw[EDIM];
        __shared__ float pb[128], pc[128];
        int tid = threadIdx.x;
        int j   = tid & 127;
        int g   = tid >> 7;

        if (tid < EDIM) sw[tid] = Wo[EDIM + tid];
        __syncthreads();

        float b = 0.f, c = 0.f;
        int i0 = g * 64;
        #pragma unroll 8
        for (int t = 0; t < 64; t++) {
            int i = i0 + t;
            float w = sw[i];
            const float* row = Wq + i * (2 * EDIM);
            b += w * row[j];
            c += w * row[EDIM + j];
        }
        if (g == 1) { pb[j] = b; pc[j] = c; }
        __syncthreads();
        if (g == 0) {
            g_a[j] = Wo[j];
            g_b[j] = b + pb[j];
            g_c[j] = c + pc[j];
        }
    } else {
        // qmin partial sweep: grid-stride int4 pairs, one plain store per block.
        __shared__ int smin[8];
        int warp = threadIdx.x >> 5;
        int lane = threadIdx.x & 31;
        int pb_i = bid - 1;
        int E4 = E >> 2;
        const int4* s4p = (const int4*)ei;
        const int4* d4p = (const int4*)(ei + E);
        int local = 0x7fffffff;
        int stride = QBLKS * 256;
        for (int i = pb_i * 256 + threadIdx.x; i < E4; i += stride) {
            int4 s = s4p[i];
            int4 d = d4p[i];
            int m0 = max(s.x, d.x), m1 = max(s.y, d.y);
            int m2 = max(s.z, d.z), m3 = max(s.w, d.w);
            local = min(local, min(min(m0, m1), min(m2, m3)));
        }
        for (int e = (E4 << 2) + pb_i * 256 + threadIdx.x; e < E; e += stride)
            local = min(local, max(ei[e], ei[E + e]));
        #pragma unroll
        for (int o = 16; o; o >>= 1)
            local = min(local, __shfl_xor_sync(0xffffffffu, local, o));
        if (lane == 0) smin[warp] = local;
        __syncthreads();
        if (threadIdx.x == 0) {
            int v = smin[0];
            #pragma unroll
            for (int w = 1; w < 8; w++) v = min(v, smin[w]);
            g_partmin[pb_i] = v;             // distinct address — no contention
        }
    }
}

// ───────────── K2: node tables, 4 nodes per warp; warp 7 reduces qmin partials
__global__ void k2_nodes(const float* __restrict__ z, const float* __restrict__ z0,
                         const float* __restrict__ bo, int N) {
    __shared__ float sa[EDIM], sb[EDIM], sc[EDIM];
    __shared__ int   sqmin;
    int warp = threadIdx.x >> 5;
    int lane = threadIdx.x & 31;

    for (int i = threadIdx.x; i < EDIM; i += blockDim.x) {
        sa[i] = g_a[i]; sb[i] = g_b[i]; sc[i] = g_c[i];
    }
    if (warp == 7) {
        int v = 0x7fffffff;
        #pragma unroll
        for (int t = 0; t < QBLKS / 32; t++) v = min(v, g_partmin[lane + 32 * t]);
        #pragma unroll
        for (int o = 16; o; o >>= 1)
            v = min(v, __shfl_xor_sync(0xffffffffu, v, o));
        if (lane == 0) sqmin = v;
    }
    __syncthreads();

    int node0 = (blockIdx.x * (blockDim.x >> 5) + warp) * 4;
    if (node0 >= N) return;

    int   qmin = sqmin;
    float bias = bo[0];
    int   k    = lane * 4;

    float4 vz[4], w4[4];
    bool   hasw[4];
    #pragma unroll
    for (int t = 0; t < 4; t++) {
        int node = node0 + t;
        int nc   = (node < N) ? node : (N - 1);
        vz[t] = ((const float4*)(z + (size_t)nc * EDIM))[lane];
        int m = nc - qmin;
        hasw[t] = (m >= 0);
        int mc = hasw[t] ? m : 0;
        w4[t] = ((const float4*)(z0 + (size_t)mc * EDIM))[lane];
    }
    #pragma unroll
    for (int t = 0; t < 4; t++) {
        int node = node0 + t;
        float s1 = vz[t].x * sa[k] + vz[t].y * sa[k+1] + vz[t].z * sa[k+2] + vz[t].w * sa[k+3];
        float s2 = vz[t].x * sb[k] + vz[t].y * sb[k+1] + vz[t].z * sb[k+2] + vz[t].w * sb[k+3];
        float s3 = hasw[t]
                 ? (w4[t].x * sc[k] + w4[t].y * sc[k+1] + w4[t].z * sc[k+2] + w4[t].w * sc[k+3])
                 : 0.f;
        #pragma unroll
        for (int o = 16; o; o >>= 1) {
            s1 += __shfl_xor_sync(0xffffffffu, s1, o);
            s2 += __shfl_xor_sync(0xffffffffu, s2, o);
            s3 += __shfl_xor_sync(0xffffffffu, s3, o);
        }
        if (lane == 0 && node < N) {
            g_T1[node] = make_float2(s1, s1 + s3);
            g_T2[node] = make_float2(s2 + bias, s2 + s3 + bias);
        }
    }
}

// ───────────── K3: per-edge output, 8 edges/thread (16 gathers in flight)
__global__ void k3_edges(const int* __restrict__ ei, float* __restrict__ out, int E) {
    int base = (blockIdx.x * blockDim.x + threadIdx.x) * 8;
    if (base + 7 < E) {
        int4 sA = *(const int4*)(ei + base);
        int4 sB = *(const int4*)(ei + base + 4);
        int4 dA = *(const int4*)(ei + E + base);
        int4 dB = *(const int4*)(ei + E + base + 4);
        int s[8] = { sA.x, sA.y, sA.z, sA.w, sB.x, sB.y, sB.z, sB.w };
        int d[8] = { dA.x, dA.y, dA.z, dA.w, dB.x, dB.y, dB.z, dB.w };
        float2 u[8], v[8];
        #pragma unroll
        for (int t = 0; t < 8; t++) u[t] = g_T1[s[t]];
        #pragma unroll
        for (int t = 0; t < 8; t++) v[t] = g_T2[d[t]];
        float r[8];
        #pragma unroll
        for (int t = 0; t < 8; t++)
            r[t] = (s[t] >= d[t]) ? (u[t].y + v[t].x) : (u[t].x + v[t].y);
        *(float4*)(out + base)     = make_float4(r[0], r[1], r[2], r[3]);
        *(float4*)(out + base + 4) = make_float4(r[4], r[5], r[6], r[7]);
    } else {
        for (int e = base; e < E; e++) {
            int ss = ei[e], dd = ei[E + e];
            float2 u = g_T1[ss];
            float2 v = g_T2[dd];
            out[e] = (ss >= dd) ? (u.y + v.x) : (u.x + v.y);
        }
    }
}

extern "C" void kernel_launch(void* const* d_in, const int* in_sizes, int n_in,
                              void* d_out, int out_size) {
    // Inputs (metadata order): z, edge_index, z0, Wq, Wo, bo
    const float* z  = (const float*)d_in[0];
    const int*   ei = (const int*)d_in[1];      // jax default int32
    const float* z0 = (const float*)d_in[2];
    const float* Wq = (const float*)d_in[3];
    const float* Wo = (const float*)d_in[4];
    const float* bo = (const float*)d_in[5];
    float* out = (float*)d_out;

    int N = in_sizes[0] / EDIM;     // 100000
    int E = in_sizes[1] / 2;        // 1000000

    k0_prep_qmin<<<1 + QBLKS, 256>>>(Wq, Wo, ei, E);
    k2_nodes<<<(N + 31) / 32, 256>>>(z, z0, bo, N);
    int threads3 = (E + 7) / 8;
    k3_edges<<<(threads3 + 255) / 256, 256>>>(ei, out, E);
}

// round 8
// speedup vs baseline: 1.1283x; 1.1283x over previous
#include <cuda_runtime.h>

#define NN      100000
#define EDIM    128
#define QBLKS   512         // qmin partial blocks (one plain-store partial each)
#define PCHUNKS 4           // prep partial chunks (4 blocks * 32 rows)

// Persistent device scratch (no allocs in kernel_launch).
__device__ float  g_a[EDIM];
__device__ float  g_part[PCHUNKS * 256];    // per-chunk partial sums: [chunk][col 0..255]
__device__ float2 g_T1[NN];                 // (s1, s1 + s3shift)
__device__ float2 g_T2[NN];                 // (s2 + bias, s2 + s3shift + bias)
__device__ int    g_partmin[QBLKS];         // per-block qmin partials

// ───────────── K0: blocks 0..3 prep partials (coalesced, 32 LDGs in flight);
//               blocks 4..4+QBLKS-1 qmin partials (int4 sweep).
__global__ void k0_prep_qmin(const float* __restrict__ Wq, const float* __restrict__ Wo,
                             const int* __restrict__ ei, int E) {
    int bid = blockIdx.x;
    int tid = threadIdx.x;

    if (bid < PCHUNKS) {
        // Partial over rows i in [bid*32, bid*32+32) for all 256 columns.
        // Thread owns column tid; 32 fully-unrolled independent coalesced loads.
        __shared__ float sw[32];
        if (tid < 32) sw[tid] = Wo[EDIM + bid * 32 + tid];
        if (bid == 0 && tid >= 128) g_a[tid - 128] = Wo[tid - 128];
        __syncthreads();

        const float* base = Wq + (size_t)(bid * 32) * (2 * EDIM) + tid;
        float acc = 0.f;
        #pragma unroll
        for (int t = 0; t < 32; t++)
            acc += sw[t] * base[t * 2 * EDIM];
        g_part[bid * 256 + tid] = acc;
    } else {
        // qmin partial sweep: grid-stride int4 pairs, one plain store per block.
        __shared__ int smin[8];
        int warp = tid >> 5;
        int lane = tid & 31;
        int pb_i = bid - PCHUNKS;
        int E4 = E >> 2;
        const int4* s4p = (const int4*)ei;
        const int4* d4p = (const int4*)(ei + E);
        int local = 0x7fffffff;
        int stride = QBLKS * 256;
        for (int i = pb_i * 256 + tid; i < E4; i += stride) {
            int4 s = s4p[i];
            int4 d = d4p[i];
            int m0 = max(s.x, d.x), m1 = max(s.y, d.y);
            int m2 = max(s.z, d.z), m3 = max(s.w, d.w);
            local = min(local, min(min(m0, m1), min(m2, m3)));
        }
        for (int e = (E4 << 2) + pb_i * 256 + tid; e < E; e += stride)
            local = min(local, max(ei[e], ei[E + e]));
        #pragma unroll
        for (int o = 16; o; o >>= 1)
            local = min(local, __shfl_xor_sync(0xffffffffu, local, o));
        if (lane == 0) smin[warp] = local;
        __syncthreads();
        if (tid == 0) {
            int v = smin[0];
            #pragma unroll
            for (int w = 1; w < 8; w++) v = min(v, smin[w]);
            g_partmin[pb_i] = v;             // distinct address — no contention
        }
    }
}

// ───────────── K2: node tables, 4 nodes/warp; fold prep partials + qmin reduce in prologue
__global__ void k2_nodes(const float* __restrict__ z, const float* __restrict__ z0,
                         const float* __restrict__ bo, int N) {
    __shared__ float sa[EDIM], sb[EDIM], sc[EDIM];
    __shared__ int   sqmin;
    int tid  = threadIdx.x;
    int warp = tid >> 5;
    int lane = tid & 31;

    // Combine the 4 prep partials (thread tid owns column tid of the 256-wide row).
    {
        float v = g_part[tid] + g_part[256 + tid] + g_part[512 + tid] + g_part[768 + tid];
        if (tid < EDIM) { sa[tid] = g_a[tid]; sb[tid] = v; }
        else            { sc[tid - EDIM] = v; }
    }
    if (warp == 7) {
        int v = 0x7fffffff;
        #pragma unroll
        for (int t = 0; t < QBLKS / 32; t++) v = min(v, g_partmin[lane + 32 * t]);
        #pragma unroll
        for (int o = 16; o; o >>= 1)
            v = min(v, __shfl_xor_sync(0xffffffffu, v, o));
        if (lane == 0) sqmin = v;
    }
    __syncthreads();

    int node0 = (blockIdx.x * (blockDim.x >> 5) + warp) * 4;
    if (node0 >= N) return;

    int   qmin = sqmin;
    float bias = bo[0];
    int   k    = lane * 4;

    float4 vz[4], w4[4];
    bool   hasw[4];
    #pragma unroll
    for (int t = 0; t < 4; t++) {
        int node = node0 + t;
        int nc   = (node < N) ? node : (N - 1);
        vz[t] = ((const float4*)(z + (size_t)nc * EDIM))[lane];
        int m = nc - qmin;
        hasw[t] = (m >= 0);
        int mc = hasw[t] ? m : 0;
        w4[t] = ((const float4*)(z0 + (size_t)mc * EDIM))[lane];
    }
    #pragma unroll
    for (int t = 0; t < 4; t++) {
        int node = node0 + t;
        float s1 = vz[t].x * sa[k] + vz[t].y * sa[k+1] + vz[t].z * sa[k+2] + vz[t].w * sa[k+3];
        float s2 = vz[t].x * sb[k] + vz[t].y * sb[k+1] + vz[t].z * sb[k+2] + vz[t].w * sb[k+3];
        float s3 = hasw[t]
                 ? (w4[t].x * sc[k] + w4[t].y * sc[k+1] + w4[t].z * sc[k+2] + w4[t].w * sc[k+3])
                 : 0.f;
        #pragma unroll
        for (int o = 16; o; o >>= 1) {
            s1 += __shfl_xor_sync(0xffffffffu, s1, o);
            s2 += __shfl_xor_sync(0xffffffffu, s2, o);
            s3 += __shfl_xor_sync(0xffffffffu, s3, o);
        }
        if (lane == 0 && node < N) {
            g_T1[node] = make_float2(s1, s1 + s3);
            g_T2[node] = make_float2(s2 + bias, s2 + s3 + bias);
        }
    }
}

// ───────────── K3: per-edge output, 8 edges/thread (16 gathers in flight)
__global__ void k3_edges(const int* __restrict__ ei, float* __restrict__ out, int E) {
    int base = (blockIdx.x * blockDim.x + threadIdx.x) * 8;
    if (base + 7 < E) {
        int4 sA = *(const int4*)(ei + base);
        int4 sB = *(const int4*)(ei + base + 4);
        int4 dA = *(const int4*)(ei + E + base);
        int4 dB = *(const int4*)(ei + E + base + 4);
        int s[8] = { sA.x, sA.y, sA.z, sA.w, sB.x, sB.y, sB.z, sB.w };
        int d[8] = { dA.x, dA.y, dA.z, dA.w, dB.x, dB.y, dB.z, dB.w };
        float2 u[8], v[8];
        #pragma unroll
        for (int t = 0; t < 8; t++) u[t] = g_T1[s[t]];
        #pragma unroll
        for (int t = 0; t < 8; t++) v[t] = g_T2[d[t]];
        float r[8];
        #pragma unroll
        for (int t = 0; t < 8; t++)
            r[t] = (s[t] >= d[t]) ? (u[t].y + v[t].x) : (u[t].x + v[t].y);
        *(float4*)(out + base)     = make_float4(r[0], r[1], r[2], r[3]);
        *(float4*)(out + base + 4) = make_float4(r[4], r[5], r[6], r[7]);
    } else {
        for (int e = base; e < E; e++) {
            int ss = ei[e], dd = ei[E + e];
            float2 u = g_T1[ss];
            float2 v = g_T2[dd];
            out[e] = (ss >= dd) ? (u.y + v.x) : (u.x + v.y);
        }
    }
}

extern "C" void kernel_launch(void* const* d_in, const int* in_sizes, int n_in,
                              void* d_out, int out_size) {
    // Inputs (metadata order): z, edge_index, z0, Wq, Wo, bo
    const float* z  = (const float*)d_in[0];
    const int*   ei = (const int*)d_in[1];      // jax default int32
    const float* z0 = (const float*)d_in[2];
    const float* Wq = (const float*)d_in[3];
    const float* Wo = (const float*)d_in[4];
    const float* bo = (const float*)d_in[5];
    float* out = (float*)d_out;

    int N = in_sizes[0] / EDIM;     // 100000
    int E = in_sizes[1] / 2;        // 1000000

    k0_prep_qmin<<<PCHUNKS + QBLKS, 256>>>(Wq, Wo, ei, E);
    k2_nodes<<<(N + 31) / 32, 256>>>(z, z0, bo, N);
    int threads3 = (E + 7) / 8;
    k3_edges<<<(threads3 + 255) / 256, 256>>>(ei, out, E);
}

// round 9
// speedup vs baseline: 1.1347x; 1.0057x over previous
#include <cuda_runtime.h>

#define NN      100000
#define EDIM    128
#define QBLKS   512         // qmin partial blocks (one plain-store partial each)
#define PCHUNKS 4           // prep partial chunks (4 blocks * 32 rows)
#define NPW     6           // nodes per warp in k2

// Persistent device scratch (no allocs in kernel_launch).
__device__ float  g_a[EDIM];
__device__ float  g_part[PCHUNKS * 256];    // per-chunk partial sums: [chunk][col 0..255]
__device__ float2 g_T1[NN];                 // (s1, s1 + s3shift)
__device__ float2 g_T2[NN];                 // (s2 + bias, s2 + s3shift + bias)
__device__ int    g_partmin[QBLKS];         // per-block qmin partials

// ───────────── K0: blocks 0..3 prep partials (coalesced, 32 LDGs in flight);
//               blocks 4..4+QBLKS-1 qmin partials (int4 sweep).
__global__ void k0_prep_qmin(const float* __restrict__ Wq, const float* __restrict__ Wo,
                             const int* __restrict__ ei, int E) {
    int bid = blockIdx.x;
    int tid = threadIdx.x;

    if (bid < PCHUNKS) {
        __shared__ float sw[32];
        if (tid < 32) sw[tid] = Wo[EDIM + bid * 32 + tid];
        if (bid == 0 && tid >= 128) g_a[tid - 128] = Wo[tid - 128];
        __syncthreads();

        const float* base = Wq + (size_t)(bid * 32) * (2 * EDIM) + tid;
        float acc = 0.f;
        #pragma unroll
        for (int t = 0; t < 32; t++)
            acc += sw[t] * base[t * 2 * EDIM];
        g_part[bid * 256 + tid] = acc;
    } else {
        __shared__ int smin[8];
        int warp = tid >> 5;
        int lane = tid & 31;
        int pb_i = bid - PCHUNKS;
        int E4 = E >> 2;
        const int4* s4p = (const int4*)ei;
        const int4* d4p = (const int4*)(ei + E);
        int local = 0x7fffffff;
        int stride = QBLKS * 256;
        for (int i = pb_i * 256 + tid; i < E4; i += stride) {
            int4 s = s4p[i];
            int4 d = d4p[i];
            int m0 = max(s.x, d.x), m1 = max(s.y, d.y);
            int m2 = max(s.z, d.z), m3 = max(s.w, d.w);
            local = min(local, min(min(m0, m1), min(m2, m3)));
        }
        for (int e = (E4 << 2) + pb_i * 256 + tid; e < E; e += stride)
            local = min(local, max(ei[e], ei[E + e]));
        #pragma unroll
        for (int o = 16; o; o >>= 1)
            local = min(local, __shfl_xor_sync(0xffffffffu, local, o));
        if (lane == 0) smin[warp] = local;
        __syncthreads();
        if (tid == 0) {
            int v = smin[0];
            #pragma unroll
            for (int w = 1; w < 8; w++) v = min(v, smin[w]);
            g_partmin[pb_i] = v;
        }
    }
}

// ───────────── K2: node tables, NPW nodes/warp (2*NPW LDG.128 in flight per warp)
__global__ void k2_nodes(const float* __restrict__ z, const float* __restrict__ z0,
                         const float* __restrict__ bo, int N) {
    __shared__ float sa[EDIM], sb[EDIM], sc[EDIM];
    __shared__ int   sqmin;
    int tid  = threadIdx.x;
    int warp = tid >> 5;
    int lane = tid & 31;

    // Combine the 4 prep partials (thread tid owns column tid of the 256-wide row).
    {
        float v = g_part[tid] + g_part[256 + tid] + g_part[512 + tid] + g_part[768 + tid];
        if (tid < EDIM) { sa[tid] = g_a[tid]; sb[tid] = v; }
        else            { sc[tid - EDIM] = v; }
    }
    if (warp == 7) {
        int v = 0x7fffffff;
        #pragma unroll
        for (int t = 0; t < QBLKS / 32; t++) v = min(v, g_partmin[lane + 32 * t]);
        #pragma unroll
        for (int o = 16; o; o >>= 1)
            v = min(v, __shfl_xor_sync(0xffffffffu, v, o));
        if (lane == 0) sqmin = v;
    }
    __syncthreads();

    int node0 = (blockIdx.x * (blockDim.x >> 5) + warp) * NPW;
    if (node0 >= N) return;

    int   qmin = sqmin;
    float bias = bo[0];
    int   k    = lane * 4;

    float4 vz[NPW], w4[NPW];
    bool   hasw[NPW];
    #pragma unroll
    for (int t = 0; t < NPW; t++) {
        int node = node0 + t;
        int nc   = (node < N) ? node : (N - 1);
        vz[t] = ((const float4*)(z + (size_t)nc * EDIM))[lane];
        int m = nc - qmin;
        hasw[t] = (m >= 0);
        int mc = hasw[t] ? m : 0;
        w4[t] = ((const float4*)(z0 + (size_t)mc * EDIM))[lane];
    }
    #pragma unroll
    for (int t = 0; t < NPW; t++) {
        int node = node0 + t;
        float s1 = vz[t].x * sa[k] + vz[t].y * sa[k+1] + vz[t].z * sa[k+2] + vz[t].w * sa[k+3];
        float s2 = vz[t].x * sb[k] + vz[t].y * sb[k+1] + vz[t].z * sb[k+2] + vz[t].w * sb[k+3];
        float s3 = hasw[t]
                 ? (w4[t].x * sc[k] + w4[t].y * sc[k+1] + w4[t].z * sc[k+2] + w4[t].w * sc[k+3])
                 : 0.f;
        #pragma unroll
        for (int o = 16; o; o >>= 1) {
            s1 += __shfl_xor_sync(0xffffffffu, s1, o);
            s2 += __shfl_xor_sync(0xffffffffu, s2, o);
            s3 += __shfl_xor_sync(0xffffffffu, s3, o);
        }
        if (lane == 0 && node < N) {
            g_T1[node] = make_float2(s1, s1 + s3);
            g_T2[node] = make_float2(s2 + bias, s2 + s3 + bias);
        }
    }
}

// ───────────── K3: per-edge output, 8 edges/thread (16 gathers in flight)
__global__ void k3_edges(const int* __restrict__ ei, float* __restrict__ out, int E) {
    int base = (blockIdx.x * blockDim.x + threadIdx.x) * 8;
    if (base + 7 < E) {
        int4 sA = *(const int4*)(ei + base);
        int4 sB = *(const int4*)(ei + base + 4);
        int4 dA = *(const int4*)(ei + E + base);
        int4 dB = *(const int4*)(ei + E + base + 4);
        int s[8] = { sA.x, sA.y, sA.z, sA.w, sB.x, sB.y, sB.z, sB.w };
        int d[8] = { dA.x, dA.y, dA.z, dA.w, dB.x, dB.y, dB.z, dB.w };
        float2 u[8], v[8];
        #pragma unroll
        for (int t = 0; t < 8; t++) u[t] = g_T1[s[t]];
        #pragma unroll
        for (int t = 0; t < 8; t++) v[t] = g_T2[d[t]];
        float r[8];
        #pragma unroll
        for (int t = 0; t < 8; t++)
            r[t] = (s[t] >= d[t]) ? (u[t].y + v[t].x) : (u[t].x + v[t].y);
        *(float4*)(out + base)     = make_float4(r[0], r[1], r[2], r[3]);
        *(float4*)(out + base + 4) = make_float4(r[4], r[5], r[6], r[7]);
    } else {
        for (int e = base; e < E; e++) {
            int ss = ei[e], dd = ei[E + e];
            float2 u = g_T1[ss];
            float2 v = g_T2[dd];
            out[e] = (ss >= dd) ? (u.y + v.x) : (u.x + v.y);
        }
    }
}

extern "C" void kernel_launch(void* const* d_in, const int* in_sizes, int n_in,
                              void* d_out, int out_size) {
    // Inputs (metadata order): z, edge_index, z0, Wq, Wo, bo
    const float* z  = (const float*)d_in[0];
    const int*   ei = (const int*)d_in[1];      // jax default int32
    const float* z0 = (const float*)d_in[2];
    const float* Wq = (const float*)d_in[3];
    const float* Wo = (const float*)d_in[4];
    const float* bo = (const float*)d_in[5];
    float* out = (float*)d_out;

    int N = in_sizes[0] / EDIM;     // 100000
    int E = in_sizes[1] / 2;        // 1000000

    k0_prep_qmin<<<PCHUNKS + QBLKS, 256>>>(Wq, Wo, ei, E);
    int nodes_per_block = NPW * 8;  // 8 warps
    k2_nodes<<<(N + nodes_per_block - 1) / nodes_per_block, 256>>>(z, z0, bo, N);
    int threads3 = (E + 7) / 8;
    k3_edges<<<(threads3 + 255) / 256, 256>>>(ei, out, E);
}